// round 13
// baseline (speedup 1.0000x reference)
#include <cuda_runtime.h>
#include <cuda_fp16.h>
#include <math.h>
#include <stdint.h>

#define NE   1024
#define NH   16
#define NKV  4
#define HD   64
#define SMAX 2048
#define BMAX 2
#define MMAX (BMAX*SMAX)
#define RMS_EPS 1.1920929e-07f
#define SM_SHIFT 13.0f

// ---------------- scratch (device globals; no allocation allowed) ----------
__device__ __half g_x[(size_t)MMAX*NE];          // x fp16
__device__ __half g_w[1536*1024];                // fused Wq|Wk|Wv fp16
__device__ __half g_wp[1024*1024];               // Wproj fp16
__device__ __half g_y[(size_t)MMAX*NE];          // attention out fp16
__device__ __half g_q[(size_t)BMAX*NH*SMAX*HD];  // roped q (scale+log2e folded)
__device__ __half g_k[(size_t)BMAX*NKV*SMAX*HD];
__device__ __half g_v[(size_t)BMAX*NKV*SMAX*HD];

// ---------------- PTX helpers (family-generic only) -------------------------
__device__ __forceinline__ uint32_t smem_to_u32(const void* p) {
    uint32_t a;
    asm("{ .reg .u64 t; cvta.to.shared.u64 t, %1; cvt.u32.u64 %0, t; }" : "=r"(a) : "l"(p));
    return a;
}
__device__ __forceinline__ void ldsm_x4(uint32_t& r0, uint32_t& r1, uint32_t& r2,
                                        uint32_t& r3, uint32_t addr) {
    asm volatile("ldmatrix.sync.aligned.m8n8.x4.shared.b16 {%0,%1,%2,%3}, [%4];"
        : "=r"(r0), "=r"(r1), "=r"(r2), "=r"(r3) : "r"(addr));
}
__device__ __forceinline__ void ldsm_x4_t(uint32_t& r0, uint32_t& r1, uint32_t& r2,
                                          uint32_t& r3, uint32_t addr) {
    asm volatile("ldmatrix.sync.aligned.m8n8.x4.trans.shared.b16 {%0,%1,%2,%3}, [%4];"
        : "=r"(r0), "=r"(r1), "=r"(r2), "=r"(r3) : "r"(addr));
}
__device__ __forceinline__ void mma_f16(float* c, const uint32_t* a, const uint32_t* b) {
    asm volatile("mma.sync.aligned.m16n8k16.row.col.f32.f16.f16.f32 "
        "{%0,%1,%2,%3}, {%4,%5,%6,%7}, {%8,%9}, {%0,%1,%2,%3};"
        : "+f"(c[0]), "+f"(c[1]), "+f"(c[2]), "+f"(c[3])
        : "r"(a[0]), "r"(a[1]), "r"(a[2]), "r"(a[3]), "r"(b[0]), "r"(b[1]));
}
__device__ __forceinline__ void cp16(uint32_t dst, const void* src) {
    asm volatile("cp.async.cg.shared.global [%0], [%1], 16;" :: "r"(dst), "l"(src));
}
#define CP_COMMIT() asm volatile("cp.async.commit_group;" ::: "memory")
#define CP_WAIT(n)  asm volatile("cp.async.wait_group %0;" :: "n"(n) : "memory")

__device__ __forceinline__ uint32_t pack_h2(float x, float y) {
    __half2 h = __floats2half2_rn(x, y);
    return *(uint32_t*)&h;
}
__device__ __forceinline__ float ex2(float x) {
    float r; asm("ex2.approx.ftz.f32 %0, %1;" : "=f"(r) : "f"(x)); return r;
}

// ---------------- merged fp32 -> fp16 convert --------------------------------
__global__ void __launch_bounds__(256) cvt_all(
    const float* __restrict__ x,  const float* __restrict__ Wq,
    const float* __restrict__ Wk, const float* __restrict__ Wv,
    const float* __restrict__ Wproj, __half* __restrict__ xo, int nx4)
{
    int i = blockIdx.x * 256 + threadIdx.x;
    const float* src;
    __half* h;
    int o;
    if (i < nx4) { src = x; h = xo; o = i; }
    else {
        i -= nx4;
        if      (i < 262144)  { src = Wq;    h = g_w;           o = i; }
        else if (i < 327680)  { src = Wk;    h = g_w + 1048576; o = i - 262144; }
        else if (i < 393216)  { src = Wv;    h = g_w + 1310720; o = i - 327680; }
        else if (i < 655360)  { src = Wproj; h = g_wp;          o = i - 393216; }
        else return;
    }
    float4 v = ((const float4*)src)[o];
    ((uint32_t*)h)[o*2]   = pack_h2(v.x, v.y);
    ((uint32_t*)h)[o*2+1] = pack_h2(v.z, v.w);
}

#define STG_BYTES 32768   /* A|B regions, 16KB each */
#define GSMEM (3*STG_BYTES)

// ================= variant A: proj GEMM, 128 thr, warp tile 64x64 ===========
__device__ __forceinline__ void gemm_issue_stage128(
    uint32_t sbase, int stg, int kc,
    const __half* __restrict__ A, const __half* __restrict__ W,
    int bm, int bn, int K, int tid)
{
    #pragma unroll
    for (int i = 0; i < 16; i++) {
        const int idx = i * 128 + tid;           // 0..2047
        const int region = idx >> 10;            // 0:A 1:W
        const int cid = idx & 1023;
        const int row = cid >> 3, c16 = cid & 7;
        const uint32_t off = row * 128 + c16 * 16;
        const uint32_t sw = off ^ ((off >> 3) & 0x70);
        const int gk = kc * 64 + c16 * 8;
        const __half* src = region ? (W + (size_t)(bn + row) * K + gk)
                                   : (A + (size_t)(bm + row) * K + gk);
        cp16(sbase + stg * STG_BYTES + region * 16384 + sw, src);
    }
}

__global__ void __launch_bounds__(128, 2) gemm_mma(
    const __half* __restrict__ A, const __half* __restrict__ W,
    float* __restrict__ C, int ldc)
{
    constexpr int K = 1024;
    constexpr int NK = K / 64;
    extern __shared__ char gsm[];
    const uint32_t sbase = smem_to_u32(gsm);
    const int tid = threadIdx.x, wid = tid >> 5, lane = tid & 31;
    const int warpM = wid & 1, warpN = wid >> 1;
    const int rIn = lane & 7, mId = lane >> 3;
    const int bm = blockIdx.y * 128, bn = blockIdx.x * 128;

    float c[4][8][4];
    #pragma unroll
    for (int mt = 0; mt < 4; mt++)
        #pragma unroll
        for (int n = 0; n < 8; n++)
            #pragma unroll
            for (int j = 0; j < 4; j++) c[mt][n][j] = 0.f;

    gemm_issue_stage128(sbase, 0, 0, A, W, bm, bn, K, tid); CP_COMMIT();
    gemm_issue_stage128(sbase, 1, 1, A, W, bm, bn, K, tid); CP_COMMIT();

    for (int kc = 0; kc < NK; kc++) {
        const int stg = kc % 3;
        if (kc + 2 < NK) {
            gemm_issue_stage128(sbase, (kc + 2) % 3, kc + 2, A, W, bm, bn, K, tid);
            CP_COMMIT();
            CP_WAIT(2);
        } else if (kc + 1 < NK) {
            CP_WAIT(1);
        } else {
            CP_WAIT(0);
        }
        __syncthreads();

        const uint32_t aA = sbase + stg * STG_BYTES;
        const uint32_t aB = aA + 16384;

        #pragma unroll
        for (int kk = 0; kk < 64; kk += 16) {
            uint32_t a[4][4];
            #pragma unroll
            for (int mt = 0; mt < 4; mt++) {
                const int row = warpM * 64 + mt * 16 + (mId & 1) * 8 + rIn;
                const int colB = (kk + (mId >> 1) * 8) * 2;
                const uint32_t off = row * 128 + colB;
                const uint32_t sw = off ^ ((off >> 3) & 0x70);
                ldsm_x4(a[mt][0], a[mt][1], a[mt][2], a[mt][3], aA + sw);
            }
            uint32_t b[8][2];
            #pragma unroll
            for (int nt = 0; nt < 4; nt++) {
                const int row = warpN * 64 + nt * 16 + (mId >> 1) * 8 + rIn;
                const int colB = (kk + (mId & 1) * 8) * 2;
                const uint32_t off = row * 128 + colB;
                const uint32_t sw = off ^ ((off >> 3) & 0x70);
                ldsm_x4(b[2*nt][0], b[2*nt][1], b[2*nt+1][0], b[2*nt+1][1], aB + sw);
            }
            #pragma unroll
            for (int mt = 0; mt < 4; mt++)
                #pragma unroll
                for (int n = 0; n < 8; n++)
                    mma_f16(c[mt][n], a[mt], b[n]);
        }
        __syncthreads();
    }

    const int g = lane >> 2, t = lane & 3;
    #pragma unroll
    for (int mt = 0; mt < 4; mt++) {
        #pragma unroll
        for (int n = 0; n < 8; n++) {
            const int r0 = bm + warpM * 64 + mt * 16 + g;
            const int col = bn + warpN * 64 + n * 8 + t * 2;
            *(float2*)&C[(size_t)r0 * ldc + col]       = make_float2(c[mt][n][0], c[mt][n][1]);
            *(float2*)&C[(size_t)(r0 + 8) * ldc + col] = make_float2(c[mt][n][2], c[mt][n][3]);
        }
    }
}

// ================= variant B: QKV GEMM, 256 thr, warp tile 32x64 ============
__device__ __forceinline__ void gemm_issue_stage256(
    uint32_t sbase, int stg, int kc,
    const __half* __restrict__ A, const __half* __restrict__ W,
    int bm, int bn, int K, int tid)
{
    #pragma unroll
    for (int i = 0; i < 8; i++) {
        const int idx = i * 256 + tid;           // 0..2047
        const int region = idx >> 10;            // 0:A 1:W
        const int cid = idx & 1023;
        const int row = cid >> 3, c16 = cid & 7;
        const uint32_t off = row * 128 + c16 * 16;
        const uint32_t sw = off ^ ((off >> 3) & 0x70);
        const int gk = kc * 64 + c16 * 8;
        const __half* src = region ? (W + (size_t)(bn + row) * K + gk)
                                   : (A + (size_t)(bm + row) * K + gk);
        cp16(sbase + stg * STG_BYTES + region * 16384 + sw, src);
    }
}

__global__ void __launch_bounds__(256, 2) gemm_qkv(
    const __half* __restrict__ A, const __half* __restrict__ W,
    const float* __restrict__ x, const float* __restrict__ ve,
    const float* __restrict__ cosb, const float* __restrict__ sinb,
    const float* __restrict__ Wgate, int S)
{
    constexpr int K = 1024;
    constexpr int NK = K / 64;
    extern __shared__ char gsm[];
    const uint32_t sbase = smem_to_u32(gsm);
    const int tid = threadIdx.x, wid = tid >> 5, lane = tid & 31;
    const int warpM = wid & 3, warpN = wid >> 2;
    const int rIn = lane & 7, mId = lane >> 3;
    const int bm = blockIdx.y * 128, bn = blockIdx.x * 128;

    float c[2][8][4];
    #pragma unroll
    for (int mt = 0; mt < 2; mt++)
        #pragma unroll
        for (int n = 0; n < 8; n++)
            #pragma unroll
            for (int j = 0; j < 4; j++) c[mt][n][j] = 0.f;

    gemm_issue_stage256(sbase, 0, 0, A, W, bm, bn, K, tid); CP_COMMIT();
    gemm_issue_stage256(sbase, 1, 1, A, W, bm, bn, K, tid); CP_COMMIT();

    for (int kc = 0; kc < NK; kc++) {
        const int stg = kc % 3;
        if (kc + 2 < NK) {
            gemm_issue_stage256(sbase, (kc + 2) % 3, kc + 2, A, W, bm, bn, K, tid);
            CP_COMMIT();
            CP_WAIT(2);
        } else if (kc + 1 < NK) {
            CP_WAIT(1);
        } else {
            CP_WAIT(0);
        }
        __syncthreads();

        const uint32_t aA = sbase + stg * STG_BYTES;
        const uint32_t aB = aA + 16384;

        #pragma unroll
        for (int kk = 0; kk < 64; kk += 16) {
            uint32_t a[2][4];
            #pragma unroll
            for (int mt = 0; mt < 2; mt++) {
                const int row = warpM * 32 + mt * 16 + (mId & 1) * 8 + rIn;
                const int colB = (kk + (mId >> 1) * 8) * 2;
                const uint32_t off = row * 128 + colB;
                const uint32_t sw = off ^ ((off >> 3) & 0x70);
                ldsm_x4(a[mt][0], a[mt][1], a[mt][2], a[mt][3], aA + sw);
            }
            uint32_t b[8][2];
            #pragma unroll
            for (int nt = 0; nt < 4; nt++) {
                const int row = warpN * 64 + nt * 16 + (mId >> 1) * 8 + rIn;
                const int colB = (kk + (mId & 1) * 8) * 2;
                const uint32_t off = row * 128 + colB;
                const uint32_t sw = off ^ ((off >> 3) & 0x70);
                ldsm_x4(b[2*nt][0], b[2*nt][1], b[2*nt+1][0], b[2*nt+1][1], aB + sw);
            }
            #pragma unroll
            for (int mt = 0; mt < 2; mt++)
                #pragma unroll
                for (int n = 0; n < 8; n++)
                    mma_f16(c[mt][n], a[mt], b[n]);
        }
        __syncthreads();
    }

    const int g = lane >> 2, t = lane & 3;
    const int colbase = bn + warpN * 64;
    const int type = (colbase < 1024) ? 0 : (colbase < 1280 ? 1 : 2);
    // q gets softmax scale and log2(e) folded in; k gets plain 1.2
    const float sQK = (type == 0) ? (1.2f * 0.125f * 1.44269504f) : 1.2f;

    #pragma unroll
    for (int mt = 0; mt < 2; mt++) {
        #pragma unroll
        for (int e = 0; e < 2; e++) {
            const int row = warpM * 32 + mt * 16 + g + e * 8;
            const int m = bm + row;
            const int b = m / S, s = m - b * S;
            if (type <= 1) {
                float r1[4][2], r2[4][2];
                float ss = 0.f;
                #pragma unroll
                for (int n = 0; n < 4; n++) {
                    const int d0 = n * 8 + 2 * t;
                    const float cs0 = cosb[s*32 + d0], cs1 = cosb[s*32 + d0 + 1];
                    const float sn0 = sinb[s*32 + d0], sn1 = sinb[s*32 + d0 + 1];
                    const float t1a = c[mt][n][2*e],   t1b = c[mt][n][2*e+1];
                    const float t2a = c[mt][n+4][2*e], t2b = c[mt][n+4][2*e+1];
                    r1[n][0] = t1a*cs0 + t2a*sn0;  r1[n][1] = t1b*cs1 + t2b*sn1;
                    r2[n][0] = t2a*cs0 - t1a*sn0;  r2[n][1] = t2b*cs1 - t1b*sn1;
                    ss += r1[n][0]*r1[n][0] + r1[n][1]*r1[n][1]
                        + r2[n][0]*r2[n][0] + r2[n][1]*r2[n][1];
                }
                ss += __shfl_xor_sync(0xffffffffu, ss, 1);
                ss += __shfl_xor_sync(0xffffffffu, ss, 2);
                const float inv = rsqrtf(ss * (1.0f/64.0f) + RMS_EPS) * sQK;
                __half* dst;
                size_t doff;
                if (type == 0) {
                    const int hh = colbase >> 6;
                    doff = ((size_t)(b*NH + hh)*S + s) * HD;
                    dst = g_q;
                } else {
                    const int kh = (colbase - 1024) >> 6;
                    doff = ((size_t)(b*NKV + kh)*S + s) * HD;
                    dst = g_k;
                }
                #pragma unroll
                for (int n = 0; n < 4; n++) {
                    const int d0 = n * 8 + 2 * t;
                    *(uint32_t*)(dst + doff + d0)      = pack_h2(r1[n][0]*inv, r1[n][1]*inv);
                    *(uint32_t*)(dst + doff + d0 + 32) = pack_h2(r2[n][0]*inv, r2[n][1]*inv);
                }
            } else {
                const int kvh = (colbase - 1280) >> 6;
                float gz = 0.f;
                #pragma unroll
                for (int j = 0; j < 3; j++)
                    gz += x[(size_t)m*NE + 3*t + j] * Wgate[kvh*12 + 3*t + j];
                gz += __shfl_xor_sync(0xffffffffu, gz, 1);
                gz += __shfl_xor_sync(0xffffffffu, gz, 2);
                const float gate = 3.0f / (1.0f + __expf(-gz));
                const size_t doff = ((size_t)(b*NKV + kvh)*S + s) * HD;
                const float* vep = ve + (size_t)m*256 + kvh*64;
                #pragma unroll
                for (int n = 0; n < 8; n++) {
                    const int d0 = n * 8 + 2 * t;
                    const float v0 = c[mt][n][2*e]   + gate * vep[d0];
                    const float v1 = c[mt][n][2*e+1] + gate * vep[d0+1];
                    *(uint32_t*)(g_v + doff + d0) = pack_h2(v0, v1);
                }
            }
        }
    }
}

// ---------------- flash attention: q-tile 128, warp = 32 rows ----------------
// MMA:LDSM ratio 4 (b/v ldsm shared across 2 fragment sets); ~45% fewer
// tile-iterations per q-row thanks to the 1024-wide window.
#define AOFF_Q   0
#define AOFF_STG 16384
#define ASTG_STRIDE 16640   /* K (8KB) + V (8KB) + amask (256B) */
#define ASMEM (AOFF_STG + 2*ASTG_STRIDE)

__device__ __forceinline__ void attn_issue_stage(
    uint32_t sbase, int buf,
    const __half* K, const __half* V, const int* amrow, int tid)
{
    const uint32_t stg = sbase + AOFF_STG + buf * ASTG_STRIDE;
    #pragma unroll
    for (int i = 0; i < 8; i++) {
        const int idx = i * 128 + tid;        // 0..1023
        const int region = idx >> 9;          // 0:K 1:V
        const int cid = idx & 511;
        const int row = cid >> 3, c16 = cid & 7;
        const uint32_t off = row * 128 + c16 * 16;
        const uint32_t sw = off ^ ((off >> 3) & 0x70);
        const __half* src = region ? (V + row * 64 + c16 * 8) : (K + row * 64 + c16 * 8);
        cp16(stg + region * 8192 + sw, src);
    }
    if (tid < 16) cp16(stg + 16384 + tid * 16, amrow + tid * 4);
}

__global__ void __launch_bounds__(128) attn_kernel(
    const int* __restrict__ amask, const int* __restrict__ lwp, int S)
{
    extern __shared__ char asm_[];
    const uint32_t sbase = smem_to_u32(asm_);
    const int q0 = blockIdx.x * 128;
    const int h  = blockIdx.y;
    const int bz = blockIdx.z;
    const int kvh = h >> 2;
    const int LW = *lwp;
    const int tid = threadIdx.x, warp = tid >> 5, lane = tid & 31;
    const int rIn = lane & 7, mId = lane >> 3;
    const int g = lane >> 2, t = lane & 3;

    const __half* Q0 = g_q + ((size_t)(bz*NH + h)*S + q0) * HD;
    const __half* K0 = g_k + ((size_t)(bz*NKV + kvh)*S) * HD;
    const __half* V0 = g_v + ((size_t)(bz*NKV + kvh)*S) * HD;
    const int* am0 = amask + bz * S;

    // Q: 128 rows -> 16KB swizzled
    #pragma unroll
    for (int i = 0; i < 8; i++) {
        const int idx = i * 128 + tid;
        const int row = idx >> 3, c16 = idx & 7;
        const uint32_t off = row * 128 + c16 * 16;
        const uint32_t sw = off ^ ((off >> 3) & 0x70);
        *(uint4*)(asm_ + AOFF_Q + sw) = *(const uint4*)(Q0 + row * 64 + c16 * 8);
    }

    int kmin = q0 - LW + 1; if (kmin < 0) kmin = 0;
    const int kt0 = kmin >> 6, kt1 = (q0 + 127) >> 6;
    const int nt = kt1 - kt0 + 1;

    attn_issue_stage(sbase, 0, K0 + (size_t)(kt0<<6)*HD, V0 + (size_t)(kt0<<6)*HD,
                     am0 + (kt0<<6), tid);
    CP_COMMIT();
    if (nt > 1) {
        attn_issue_stage(sbase, 1, K0 + (size_t)((kt0+1)<<6)*HD, V0 + (size_t)((kt0+1)<<6)*HD,
                         am0 + ((kt0+1)<<6), tid);
        CP_COMMIT();
    }

    __syncthreads();

    // Q a-frags for 2 sets of 16 rows (warp covers rows warp*32 .. +31)
    uint32_t aq[2][4][4];
    #pragma unroll
    for (int s = 0; s < 2; s++) {
        #pragma unroll
        for (int kk = 0; kk < 4; kk++) {
            const int row = warp * 32 + s * 16 + (mId & 1) * 8 + rIn;
            const int colB = (kk * 16 + (mId >> 1) * 8) * 2;
            const uint32_t off = row * 128 + colB;
            const uint32_t sw = off ^ ((off >> 3) & 0x70);
            ldsm_x4(aq[s][kk][0], aq[s][kk][1], aq[s][kk][2], aq[s][kk][3],
                    sbase + AOFF_Q + sw);
        }
    }

    float o[2][8][4];
    #pragma unroll
    for (int s = 0; s < 2; s++)
        #pragma unroll
        for (int j = 0; j < 8; j++)
            #pragma unroll
            for (int e = 0; e < 4; e++) o[s][j][e] = 0.f;
    float l[2][2] = {{0.f, 0.f}, {0.f, 0.f}};
    const int rowlow  = q0 + warp * 32;
    const int rowhigh = rowlow + 31;

    for (int i = 0; i < nt; i++) {
        const int kt = kt0 + i, buf = i & 1;
        const int k0 = kt << 6;
        if (i + 1 < nt) { CP_WAIT(1); } else { CP_WAIT(0); }
        __syncthreads();

        const uint32_t stg = sbase + AOFF_STG + buf * ASTG_STRIDE;
        const uint32_t sK = stg, sV = stg + 8192;
        const int* sAm = (const int*)(asm_ + AOFF_STG + buf * ASTG_STRIDE + 16384);

        float sc[2][8][4];
        #pragma unroll
        for (int s = 0; s < 2; s++)
            #pragma unroll
            for (int j = 0; j < 8; j++)
                #pragma unroll
                for (int e = 0; e < 4; e++) sc[s][j][e] = 0.f;

        #pragma unroll
        for (int kk = 0; kk < 4; kk++) {
            uint32_t b[8][2];
            #pragma unroll
            for (int ntp = 0; ntp < 4; ntp++) {
                const int row = ntp * 16 + (mId >> 1) * 8 + rIn;
                const int colB = (kk * 16 + (mId & 1) * 8) * 2;
                const uint32_t off = row * 128 + colB;
                const uint32_t sw = off ^ ((off >> 3) & 0x70);
                ldsm_x4(b[2*ntp][0], b[2*ntp][1], b[2*ntp+1][0], b[2*ntp+1][1], sK + sw);
            }
            #pragma unroll
            for (int s = 0; s < 2; s++)
                #pragma unroll
                for (int j = 0; j < 8; j++)
                    mma_f16(sc[s][j], aq[s][kk], b[j]);
        }

        // warp-uniform interior test
        const bool mask_ok = (sAm[lane] != 0) && (sAm[32 + lane] != 0);
        const bool fast = (k0 + 63 <= rowlow) && (rowhigh - k0 < LW) &&
                          __all_sync(0xffffffffu, mask_ok);

        if (fast) {
            #pragma unroll
            for (int s = 0; s < 2; s++) {
                #pragma unroll
                for (int j = 0; j < 8; j++) {
                    const float p0 = ex2(sc[s][j][0] - SM_SHIFT);
                    const float p1 = ex2(sc[s][j][1] - SM_SHIFT);
                    const float p2 = ex2(sc[s][j][2] - SM_SHIFT);
                    const float p3 = ex2(sc[s][j][3] - SM_SHIFT);
                    sc[s][j][0] = p0; sc[s][j][1] = p1; sc[s][j][2] = p2; sc[s][j][3] = p3;
                    l[s][0] += p0 + p1; l[s][1] += p2 + p3;
                }
            }
        } else {
            #pragma unroll
            for (int s = 0; s < 2; s++) {
                const int r0g = rowlow + s * 16 + g;
                const int r1g = r0g + 8;
                #pragma unroll
                for (int j = 0; j < 8; j++) {
                    const int ce = 8*j + 2*t, co = ce + 1;
                    const int ae = sAm[ce], ao = sAm[co];
                    const int gce = k0 + ce, gco = k0 + co;
                    const bool a0 = ((unsigned)(r0g - gce) < (unsigned)LW) && (ae != 0);
                    const bool a1 = ((unsigned)(r0g - gco) < (unsigned)LW) && (ao != 0);
                    const bool a2 = ((unsigned)(r1g - gce) < (unsigned)LW) && (ae != 0);
                    const bool a3 = ((unsigned)(r1g - gco) < (unsigned)LW) && (ao != 0);
                    const float p0 = a0 ? ex2(sc[s][j][0] - SM_SHIFT) : 0.f;
                    const float p1 = a1 ? ex2(sc[s][j][1] - SM_SHIFT) : 0.f;
                    const float p2 = a2 ? ex2(sc[s][j][2] - SM_SHIFT) : 0.f;
                    const float p3 = a3 ? ex2(sc[s][j][3] - SM_SHIFT) : 0.f;
                    sc[s][j][0] = p0; sc[s][j][1] = p1; sc[s][j][2] = p2; sc[s][j][3] = p3;
                    l[s][0] += p0 + p1; l[s][1] += p2 + p3;
                }
            }
        }

        // PV: per kb load v once, pack pa transiently per set, 16 MMA
        #pragma unroll
        for (int kb = 0; kb < 4; kb++) {
            uint32_t v[8][2];
            #pragma unroll
            for (int dp = 0; dp < 4; dp++) {
                const int row = kb * 16 + (mId & 1) * 8 + rIn;
                const int colB = (dp * 16 + (mId >> 1) * 8) * 2;
                const uint32_t off = row * 128 + colB;
                const uint32_t sw = off ^ ((off >> 3) & 0x70);
                ldsm_x4_t(v[2*dp][0], v[2*dp][1], v[2*dp+1][0], v[2*dp+1][1], sV + sw);
            }
            #pragma unroll
            for (int s = 0; s < 2; s++) {
                uint32_t pa[4];
                const int j0 = 2*kb, j1 = 2*kb + 1;
                pa[0] = pack_h2(sc[s][j0][0], sc[s][j0][1]);
                pa[1] = pack_h2(sc[s][j0][2], sc[s][j0][3]);
                pa[2] = pack_h2(sc[s][j1][0], sc[s][j1][1]);
                pa[3] = pack_h2(sc[s][j1][2], sc[s][j1][3]);
                #pragma unroll
                for (int j = 0; j < 8; j++)
                    mma_f16(o[s][j], pa, v[j]);
            }
        }

        __syncthreads();
        if (i + 2 < nt) {
            const int kn = (kt + 2) << 6;
            attn_issue_stage(sbase, buf, K0 + (size_t)kn*HD, V0 + (size_t)kn*HD,
                             am0 + kn, tid);
            CP_COMMIT();
        }
    }

    #pragma unroll
    for (int s = 0; s < 2; s++) {
        float l0 = l[s][0], l1 = l[s][1];
        l0 += __shfl_xor_sync(0xffffffffu, l0, 1);
        l0 += __shfl_xor_sync(0xffffffffu, l0, 2);
        l1 += __shfl_xor_sync(0xffffffffu, l1, 1);
        l1 += __shfl_xor_sync(0xffffffffu, l1, 2);
        const float inv0 = 1.0f / l0, inv1 = 1.0f / l1;
        const int r0g = rowlow + s * 16 + g;
        const int r1g = r0g + 8;
        const size_t tok0 = (size_t)(bz*S + r0g) * NE + h*HD;
        const size_t tok1 = (size_t)(bz*S + r1g) * NE + h*HD;
        #pragma unroll
        for (int j = 0; j < 8; j++) {
            const int d0 = 8*j + 2*t;
            *(uint32_t*)(g_y + tok0 + d0) = pack_h2(o[s][j][0]*inv0, o[s][j][1]*inv0);
            *(uint32_t*)(g_y + tok1 + d0) = pack_h2(o[s][j][2]*inv1, o[s][j][3]*inv1);
        }
    }
}

// ---------------- launch ----------------------------------------------------
extern "C" void kernel_launch(void* const* d_in, const int* in_sizes, int n_in,
                              void* d_out, int out_size)
{
    const float* x     = (const float*)d_in[0];
    const float* ve    = (const float*)d_in[1];
    const float* cosb  = (const float*)d_in[2];
    const float* sinb  = (const float*)d_in[3];
    const float* Wq    = (const float*)d_in[4];
    const float* Wk    = (const float*)d_in[5];
    const float* Wv    = (const float*)d_in[6];
    const float* Wproj = (const float*)d_in[7];
    const float* Wgate = (const float*)d_in[8];
    const int*   amask = (const int*)d_in[9];
    const int*   lw    = (const int*)d_in[10];
    float* out = (float*)d_out;

    const int S = in_sizes[2] / 32;        // cos is (S,1,32)
    const int B = in_sizes[0] / (S * NE);
    const int M = B * S;

    __half *xp, *wp, *wpp, *yp;
    cudaGetSymbolAddress((void**)&xp,  g_x);
    cudaGetSymbolAddress((void**)&wp,  g_w);
    cudaGetSymbolAddress((void**)&wpp, g_wp);
    cudaGetSymbolAddress((void**)&yp,  g_y);

    // merged fp32 -> fp16 converts
    const int nx4 = M * NE / 4;
    const int ntot = nx4 + 655360;
    cvt_all<<<(ntot + 255)/256, 256>>>(x, Wq, Wk, Wv, Wproj, xp, nx4);

    cudaFuncSetAttribute(gemm_qkv, cudaFuncAttributeMaxDynamicSharedMemorySize, GSMEM);
    cudaFuncSetAttribute(gemm_mma, cudaFuncAttributeMaxDynamicSharedMemorySize, GSMEM);

    // fused QKV projection + rope/rmsnorm/gate epilogue (32x64 warp tile)
    gemm_qkv<<<dim3(12, M/128), 256, GSMEM>>>(xp, wp, x, ve, cosb, sinb, Wgate, S);

    // attention (q-tile 128, warp = 32 rows, fixed-shift softmax, fast path)
    cudaFuncSetAttribute(attn_kernel, cudaFuncAttributeMaxDynamicSharedMemorySize, ASMEM);
    attn_kernel<<<dim3(S/128, NH, B), 128, ASMEM>>>(amask, lw, S);

    // output projection (64x64 warp tile) straight into d_out
    gemm_mma<<<dim3(8, M/128), 128, GSMEM>>>(yp, wpp, out, 1024);
}